// round 1
// baseline (speedup 1.0000x reference)
#include <cuda_runtime.h>
#include <math.h>
#include <float.h>

// Problem constants
#define NPAIR 1024          // B*R = 16*64
#define NOBJ  32
#define SIZE  64
// conv1: 2->64, 5x5 VALID: 64 -> 60, pool -> 30
// conv2: 64->32, 5x5 VALID: 30 -> 26, pool -> 13, mean, fc 32->512

// ---------------- scratch (static device globals: no allocation in kernel_launch) ---------
__device__ float g_pool1[NPAIR * 64 * 900];   // [pair][ch64][30][30]  (~236MB)
__device__ float g_w2t[64 * 25 * 32];         // conv2 weights transposed: [c][p][q][o]
__device__ float g_P[128 * 36];               // conv1 SAT: [(o*2+c)][6][6]

// --------- exact integerization of mask intervals -----------
// smallest integer x with (x+0.5f >= t)
__device__ __forceinline__ int lo_int(float t) {
    int a = (int)ceilf(t - 0.5f);
    if ((float)a + 0.5f < t) a++;
    else if ((float)(a - 1) + 0.5f >= t) a--;
    return a;
}
// largest integer x with (x+0.5f <= t)
__device__ __forceinline__ int hi_int(float t) {
    int b = (int)floorf(t - 0.5f);
    if ((float)b + 0.5f > t) b--;
    else if ((float)(b + 1) + 0.5f <= t) b++;
    return b;
}

// SAT rectangle sum: sum of w[p][q] for p in window overlap with [Ay,By], q with [Ax,Bx]
__device__ __forceinline__ float satv(const float* __restrict__ P,
                                      int Ay, int By, int Ax, int Bx, int i, int j) {
    int pl = min(max(Ay - i, 0), 5);
    int ph = min(max(By - i + 1, 0), 5);
    ph = max(ph, pl);
    int ql = min(max(Ax - j, 0), 5);
    int qh = min(max(Bx - j + 1, 0), 5);
    qh = max(qh, ql);
    return P[ph * 6 + qh] - P[pl * 6 + qh] - P[ph * 6 + ql] + P[pl * 6 + ql];
}

// ---------------- K0: prep (weight transpose + conv1 SAT build) ----------------
__global__ void prep_kernel(const float* __restrict__ conv2_w,
                            const float* __restrict__ conv1_w) {
    int idx = blockIdx.x * blockDim.x + threadIdx.x;
    if (idx < 64 * 25 * 32) {
        // g_w2t[(c*25+pq)*32 + o] = conv2_w[(o*64 + c)*25 + pq]
        int o = idx & 31;
        int t2 = idx >> 5;
        int pq = t2 % 25;
        int c = t2 / 25;
        g_w2t[idx] = conv2_w[(o * 64 + c) * 25 + pq];
    } else if (idx < 64 * 25 * 32 + 128) {
        int u = idx - 64 * 25 * 32;   // u = o*2 + c
        const float* w = conv1_w + u * 25;
        float P[36];
        #pragma unroll
        for (int k = 0; k < 6; k++) { P[k] = 0.0f; P[k * 6] = 0.0f; }
        for (int a = 1; a < 6; a++)
            for (int b = 1; b < 6; b++)
                P[a * 6 + b] = P[(a - 1) * 6 + b] + P[a * 6 + b - 1]
                             - P[(a - 1) * 6 + b - 1] + w[(a - 1) * 5 + (b - 1)];
        for (int k = 0; k < 36; k++) g_P[u * 36 + k] = P[k];
    }
}

// ---------------- K1: rasterize + conv1 (via SAT) + maxpool2 -> g_pool1 ----------------
__global__ __launch_bounds__(256) void pool1_kernel(
    const float* __restrict__ bboxes,
    const int* __restrict__ object_pairs,
    const float* __restrict__ conv1_b) {
    __shared__ float Psm[128 * 36];
    __shared__ float bsm[64];

    int tid = threadIdx.x;
    int pair = blockIdx.x;

    for (int k = tid; k < 128 * 36; k += 256) Psm[k] = g_P[k];
    if (tid < 64) bsm[tid] = conv1_b[tid];

    // per-pair box params (computed redundantly by all threads; cheap)
    int bidx = pair >> 6;   // pair = b*64 + r
    int i0 = object_pairs[pair * 2 + 0];
    int i1 = object_pairs[pair * 2 + 1];
    const float* p0 = bboxes + (bidx * NOBJ + i0) * 4;
    const float* p1 = bboxes + (bidx * NOBJ + i1) * 4;
    float b0x1 = p0[0], b0y1 = p0[1], b0x2 = p0[2], b0y2 = p0[3];
    float b1x1 = p1[0], b1y1 = p1[1], b1x2 = p1[2], b1y2 = p1[3];
    float ux1 = fminf(b0x1, b1x1), uy1 = fminf(b0y1, b1y1);
    float ux2 = fmaxf(b0x2, b1x2), uy2 = fmaxf(b0y2, b1y2);
    float uw = fmaxf(ux2 - ux1, 1e-6f), uh = fmaxf(uy2 - uy1, 1e-6f);

    int Ax0, Bx0, Ay0, By0, Ax1, Bx1, Ay1, By1;
    {
        float sx1 = (b0x1 - ux1) / uw * 64.0f, sy1 = (b0y1 - uy1) / uh * 64.0f;
        float sx2 = (b0x2 - ux1) / uw * 64.0f, sy2 = (b0y2 - uy1) / uh * 64.0f;
        Ax0 = lo_int(sx1); Bx0 = hi_int(sx2); Ay0 = lo_int(sy1); By0 = hi_int(sy2);
    }
    {
        float sx1 = (b1x1 - ux1) / uw * 64.0f, sy1 = (b1y1 - uy1) / uh * 64.0f;
        float sx2 = (b1x2 - ux1) / uw * 64.0f, sy2 = (b1y2 - uy1) / uh * 64.0f;
        Ax1 = lo_int(sx1); Bx1 = hi_int(sx2); Ay1 = lo_int(sy1); By1 = hi_int(sy2);
    }
    __syncthreads();

    for (int t = tid; t < 64 * 900; t += 256) {
        int o = t / 900;
        int r = t - o * 900;
        int pi = r / 30;
        int pj = r - pi * 30;
        const float* P0 = Psm + o * 72;
        const float* P1 = P0 + 36;
        float m = -FLT_MAX;
        #pragma unroll
        for (int di = 0; di < 2; di++) {
            #pragma unroll
            for (int dj = 0; dj < 2; dj++) {
                int i = 2 * pi + di, j = 2 * pj + dj;
                float v = satv(P0, Ay0, By0, Ax0, Bx0, i, j)
                        + satv(P1, Ay1, By1, Ax1, Bx1, i, j);
                m = fmaxf(m, v);
            }
        }
        g_pool1[pair * 57600 + t] = m + bsm[o];
    }
}

// ---------------- K2: conv2 + pool2 + mean + fc + relu ----------------
// block = one pair. blockDim = (32, 8). Thread (tx,ty): output row tx (<26), out-channels ty*4..+3.
// dynamic smem: in_sm [32ch][30 rows][pitch 33] + w_sm [32c*25pq][32o] + mean_sm[32]
#define IN_SM_F  (32 * 30 * 33)     // 31680 floats
#define W_SM_F   (32 * 25 * 32)     // 25600 floats
#define SMEM_F   (IN_SM_F + W_SM_F + 32)
#define SMEM_BYTES (SMEM_F * 4)

__global__ __launch_bounds__(256) void conv2_kernel(
    const float* __restrict__ conv2_b,
    const float* __restrict__ fc_w,
    const float* __restrict__ fc_b,
    float* __restrict__ out) {
    extern __shared__ float sm[];
    float* in_sm = sm;
    float* w_sm = sm + IN_SM_F;
    float* mean_sm = sm + IN_SM_F + W_SM_F;

    int tx = threadIdx.x, ty = threadIdx.y;
    int tid = ty * 32 + tx;
    int pair = blockIdx.x;

    float acc0[26], acc1[26], acc2[26], acc3[26];
    #pragma unroll
    for (int j = 0; j < 26; j++) { acc0[j] = 0.f; acc1[j] = 0.f; acc2[j] = 0.f; acc3[j] = 0.f; }

    for (int cc = 0; cc < 2; cc++) {
        __syncthreads();   // protect previous chunk reads before overwrite (no-op first iter)
        for (int idx = tid; idx < 32 * 900; idx += 256) {
            int c = idx / 900;
            int rc = idx - c * 900;
            int row = rc / 30;
            int col = rc - row * 30;
            in_sm[c * 990 + row * 33 + col] = g_pool1[pair * 57600 + cc * 28800 + idx];
        }
        for (int idx = tid; idx < W_SM_F; idx += 256)
            w_sm[idx] = g_w2t[cc * W_SM_F + idx];
        __syncthreads();

        if (tx < 26) {
            #pragma unroll 1
            for (int c = 0; c < 32; c++) {
                #pragma unroll 1
                for (int p = 0; p < 5; p++) {
                    const float* rp = in_sm + c * 990 + (tx + p) * 33;
                    float xin[30];
                    #pragma unroll
                    for (int j = 0; j < 30; j++) xin[j] = rp[j];
                    const float* wb = w_sm + (c * 5 + p) * 5 * 32 + ty * 4;
                    #pragma unroll
                    for (int q = 0; q < 5; q++) {
                        float4 wv = *(const float4*)(wb + q * 32);
                        #pragma unroll
                        for (int j = 0; j < 26; j++) {
                            float x = xin[j + q];
                            acc0[j] = fmaf(x, wv.x, acc0[j]);
                            acc1[j] = fmaf(x, wv.y, acc1[j]);
                            acc2[j] = fmaf(x, wv.z, acc2[j]);
                            acc3[j] = fmaf(x, wv.w, acc3[j]);
                        }
                    }
                }
            }
        }
    }
    __syncthreads();

    // write conv2 outputs (+bias) to smem: conv_sm[o][row(26)][col(26)], reuse in_sm space
    float* conv_sm = sm;
    if (tx < 26) {
        float b0 = __ldg(&conv2_b[ty * 4 + 0]);
        float b1 = __ldg(&conv2_b[ty * 4 + 1]);
        float b2 = __ldg(&conv2_b[ty * 4 + 2]);
        float b3 = __ldg(&conv2_b[ty * 4 + 3]);
        #pragma unroll
        for (int j = 0; j < 26; j++) {
            conv_sm[((ty * 4 + 0) * 26 + tx) * 26 + j] = acc0[j] + b0;
            conv_sm[((ty * 4 + 1) * 26 + tx) * 26 + j] = acc1[j] + b1;
            conv_sm[((ty * 4 + 2) * 26 + tx) * 26 + j] = acc2[j] + b2;
            conv_sm[((ty * 4 + 3) * 26 + tx) * 26 + j] = acc3[j] + b3;
        }
    }
    __syncthreads();

    // pool2 (2x2 max) + spatial mean, per-warp (warp = ty), deterministic shuffle reduce
    #pragma unroll
    for (int oo = 0; oo < 4; oo++) {
        int o = ty * 4 + oo;
        float s = 0.0f;
        for (int idx = tx; idx < 169; idx += 32) {
            int pi = idx / 13;
            int pj = idx - pi * 13;
            const float* b = conv_sm + (o * 26 + 2 * pi) * 26 + 2 * pj;
            float m = fmaxf(fmaxf(b[0], b[1]), fmaxf(b[26], b[27]));
            s += m;
        }
        #pragma unroll
        for (int off = 16; off; off >>= 1) s += __shfl_down_sync(0xffffffffu, s, off);
        if (tx == 0) mean_sm[o] = s * (1.0f / 169.0f);
    }
    __syncthreads();

    // fc (32 -> 512) + relu
    for (int k = tid; k < 512; k += 256) {
        float v = __ldg(&fc_b[k]);
        const float4* fw = (const float4*)(fc_w + k * 32);
        #pragma unroll
        for (int c4 = 0; c4 < 8; c4++) {
            float4 w4 = __ldg(&fw[c4]);
            v = fmaf(mean_sm[c4 * 4 + 0], w4.x, v);
            v = fmaf(mean_sm[c4 * 4 + 1], w4.y, v);
            v = fmaf(mean_sm[c4 * 4 + 2], w4.z, v);
            v = fmaf(mean_sm[c4 * 4 + 3], w4.w, v);
        }
        out[pair * 512 + k] = fmaxf(v, 0.0f);
    }
}

// ---------------- launch ----------------
extern "C" void kernel_launch(void* const* d_in, const int* in_sizes, int n_in,
                              void* d_out, int out_size) {
    const float* bboxes       = (const float*)d_in[0];   // (16,32,4)
    // d_in[1] num_obj, d_in[2] num_relation: unused by reference
    const int*   object_pairs = (const int*)d_in[3];     // (16,64,2)
    const float* conv1_w      = (const float*)d_in[4];   // (64,2,5,5)
    const float* conv1_b      = (const float*)d_in[5];   // (64)
    const float* conv2_w      = (const float*)d_in[6];   // (32,64,5,5)
    const float* conv2_b      = (const float*)d_in[7];   // (32)
    const float* fc_w         = (const float*)d_in[8];   // (512,32)
    const float* fc_b         = (const float*)d_in[9];   // (512)
    float* out = (float*)d_out;                          // (1024,512)

    static int attr_set = 0;
    if (!attr_set) {
        cudaFuncSetAttribute(conv2_kernel, cudaFuncAttributeMaxDynamicSharedMemorySize, SMEM_BYTES);
        attr_set = 1;
    }

    prep_kernel<<<(64 * 25 * 32 + 128 + 255) / 256, 256>>>(conv2_w, conv1_w);
    pool1_kernel<<<NPAIR, 256>>>(bboxes, object_pairs, conv1_b);
    conv2_kernel<<<NPAIR, dim3(32, 8), SMEM_BYTES>>>(conv2_b, fc_w, fc_b, out);
}

// round 2
// speedup vs baseline: 1.0919x; 1.0919x over previous
#include <cuda_runtime.h>
#include <math.h>
#include <float.h>

// Problem constants
#define NPAIR 1024          // B*R = 16*64
#define NOBJ  32
// conv1: 2->64, 5x5 VALID: 64 -> 60, pool -> 30
// conv2: 64->32, 5x5 VALID: 30 -> 26, pool -> 13, mean, fc 32->512

// ---------------- persistent prep scratch ----------------
__device__ float g_w2t[64 * 25 * 32];   // conv2 weights transposed: [c][p][q][o]
__device__ float g_P[128 * 36];         // conv1 SAT: [(o*2+box)][6][6]

// packed fp32x2 FMA (sm_103a): one issue slot = 2 fp32 FMAs
#define FMA2(acc, x, w) \
    asm("fma.rn.f32x2 %0, %1, %2, %0;" : "+l"(acc) : "l"(x), "l"(w))

// --------- exact integerization of mask intervals -----------
__device__ __forceinline__ int lo_int(float t) {   // smallest x with (x+0.5f >= t)
    int a = (int)ceilf(t - 0.5f);
    if ((float)a + 0.5f < t) a++;
    else if ((float)(a - 1) + 0.5f >= t) a--;
    return a;
}
__device__ __forceinline__ int hi_int(float t) {   // largest x with (x+0.5f <= t)
    int b = (int)floorf(t - 0.5f);
    if ((float)b + 0.5f > t) b--;
    else if ((float)(b + 1) + 0.5f <= t) b++;
    return b;
}

__device__ __forceinline__ float satv(const float* __restrict__ P,
                                      int Ay, int By, int Ax, int Bx, int i, int j) {
    int pl = min(max(Ay - i, 0), 5);
    int ph = min(max(By - i + 1, 0), 5);
    ph = max(ph, pl);
    int ql = min(max(Ax - j, 0), 5);
    int qh = min(max(Bx - j + 1, 0), 5);
    qh = max(qh, ql);
    return P[ph * 6 + qh] - P[pl * 6 + qh] - P[ph * 6 + ql] + P[pl * 6 + ql];
}

// ---------------- K0: prep (weight transpose + conv1 SAT build) ----------------
__global__ void prep_kernel(const float* __restrict__ conv2_w,
                            const float* __restrict__ conv1_w) {
    int idx = blockIdx.x * blockDim.x + threadIdx.x;
    if (idx < 64 * 25 * 32) {
        int o = idx & 31;
        int t2 = idx >> 5;
        int pq = t2 % 25;
        int c = t2 / 25;
        g_w2t[idx] = conv2_w[(o * 64 + c) * 25 + pq];
    } else if (idx < 64 * 25 * 32 + 128) {
        int u = idx - 64 * 25 * 32;
        const float* w = conv1_w + u * 25;
        float P[36];
        #pragma unroll
        for (int k = 0; k < 6; k++) { P[k] = 0.0f; P[k * 6] = 0.0f; }
        for (int a = 1; a < 6; a++)
            for (int b = 1; b < 6; b++)
                P[a * 6 + b] = P[(a - 1) * 6 + b] + P[a * 6 + b - 1]
                             - P[(a - 1) * 6 + b - 1] + w[(a - 1) * 5 + (b - 1)];
        for (int k = 0; k < 36; k++) g_P[u * 36 + k] = P[k];
    }
}

// ---------------- K1: fused rasterize+conv1+pool1 + conv2 + pool2 + mean + fc + relu ----
// block = one pair. blockDim = (32, 8). Thread (tx,ty): output row tx (<26), out-ch ty*4..+3.
// 4 channel-chunks of 16. Input stored DUPLICATED as float2 {v,v}: LDS.64 gives the packed
// f32x2 operand directly. Weights for adjacent out-channels adjacent -> LDS.64 packed.
#define CH_CHUNK 16
#define ROWP     31                         // row pitch in float2 (odd -> conflict-free)
#define IN_SM_F2 (CH_CHUNK * 30 * ROWP)     // 14880 float2 = 119040 B
#define W_SM_F   (CH_CHUNK * 25 * 32)       // 12800 floats = 51200 B
#define SMEM_BYTES (IN_SM_F2 * 8 + W_SM_F * 4 + 32 * 4)

typedef unsigned long long ull;
__device__ __forceinline__ float lo_f(ull v) { return __uint_as_float((unsigned)v); }
__device__ __forceinline__ float hi_f(ull v) { return __uint_as_float((unsigned)(v >> 32)); }

__global__ __launch_bounds__(256) void fused_kernel(
    const float* __restrict__ bboxes,
    const int* __restrict__ object_pairs,
    const float* __restrict__ conv1_b,
    const float* __restrict__ conv2_b,
    const float* __restrict__ fc_w,
    const float* __restrict__ fc_b,
    float* __restrict__ out) {
    extern __shared__ float sm[];
    float2* in_sm = (float2*)sm;                       // duplicated input chunk
    float*  w_sm  = sm + IN_SM_F2 * 2;                 // weight chunk
    float*  mean_sm = w_sm + W_SM_F;

    __shared__ float Psm[128 * 36];
    __shared__ float bsm[64];

    int tx = threadIdx.x, ty = threadIdx.y;
    int tid = ty * 32 + tx;
    int pair = blockIdx.x;

    for (int k = tid; k < 128 * 36; k += 256) Psm[k] = g_P[k];
    if (tid < 64) bsm[tid] = conv1_b[tid];

    // per-pair box params (computed redundantly; cheap)
    int bidx = pair >> 6;
    int i0 = object_pairs[pair * 2 + 0];
    int i1 = object_pairs[pair * 2 + 1];
    const float* p0 = bboxes + (bidx * NOBJ + i0) * 4;
    const float* p1 = bboxes + (bidx * NOBJ + i1) * 4;
    float b0x1 = p0[0], b0y1 = p0[1], b0x2 = p0[2], b0y2 = p0[3];
    float b1x1 = p1[0], b1y1 = p1[1], b1x2 = p1[2], b1y2 = p1[3];
    float ux1 = fminf(b0x1, b1x1), uy1 = fminf(b0y1, b1y1);
    float ux2 = fmaxf(b0x2, b1x2), uy2 = fmaxf(b0y2, b1y2);
    float uw = fmaxf(ux2 - ux1, 1e-6f), uh = fmaxf(uy2 - uy1, 1e-6f);

    int Ax0, Bx0, Ay0, By0, Ax1, Bx1, Ay1, By1;
    {
        float sx1 = (b0x1 - ux1) / uw * 64.0f, sy1 = (b0y1 - uy1) / uh * 64.0f;
        float sx2 = (b0x2 - ux1) / uw * 64.0f, sy2 = (b0y2 - uy1) / uh * 64.0f;
        Ax0 = lo_int(sx1); Bx0 = hi_int(sx2); Ay0 = lo_int(sy1); By0 = hi_int(sy2);
    }
    {
        float sx1 = (b1x1 - ux1) / uw * 64.0f, sy1 = (b1y1 - uy1) / uh * 64.0f;
        float sx2 = (b1x2 - ux1) / uw * 64.0f, sy2 = (b1y2 - uy1) / uh * 64.0f;
        Ax1 = lo_int(sx1); Bx1 = hi_int(sx2); Ay1 = lo_int(sy1); By1 = hi_int(sy2);
    }

    ull accA[26], accB[26];
    #pragma unroll
    for (int j = 0; j < 26; j++) { accA[j] = 0ull; accB[j] = 0ull; }

    #pragma unroll 1
    for (int cc = 0; cc < 4; cc++) {
        __syncthreads();    // protect prior chunk reads; also orders Psm/bsm on first iter

        // ---- build pool1 chunk (conv1 via SAT + 2x2 maxpool) directly in smem, duplicated
        for (int t = tid; t < CH_CHUNK * 900; t += 256) {
            int c  = t / 900;                 // local channel
            int cg = cc * CH_CHUNK + c;       // global conv1 out-channel
            int r  = t - c * 900;
            int pi = r / 30;
            int pj = r - pi * 30;
            const float* P0 = Psm + cg * 72;
            const float* P1 = P0 + 36;
            float m = -FLT_MAX;
            #pragma unroll
            for (int di = 0; di < 2; di++) {
                #pragma unroll
                for (int dj = 0; dj < 2; dj++) {
                    int i = 2 * pi + di, j = 2 * pj + dj;
                    float v = satv(P0, Ay0, By0, Ax0, Bx0, i, j)
                            + satv(P1, Ay1, By1, Ax1, Bx1, i, j);
                    m = fmaxf(m, v);
                }
            }
            float val = m + bsm[cg];
            in_sm[c * (30 * ROWP) + pi * ROWP + pj] = make_float2(val, val);
        }
        // ---- weight chunk
        for (int idx = tid; idx < W_SM_F; idx += 256)
            w_sm[idx] = g_w2t[cc * W_SM_F + idx];
        __syncthreads();

        // ---- conv2 partial sums, packed over output-channel pairs
        if (tx < 26) {
            #pragma unroll 1
            for (int c = 0; c < CH_CHUNK; c++) {
                #pragma unroll 1
                for (int p = 0; p < 5; p++) {
                    const ull* rp = (const ull*)(in_sm + c * (30 * ROWP) + (tx + p) * ROWP);
                    ull xd[30];
                    #pragma unroll
                    for (int j = 0; j < 30; j++) xd[j] = rp[j];
                    const float* wb = w_sm + (c * 25 + p * 5) * 32 + ty * 4;
                    #pragma unroll
                    for (int q = 0; q < 5; q++) {
                        ull wA = *(const ull*)(wb + q * 32);
                        ull wB = *(const ull*)(wb + q * 32 + 2);
                        #pragma unroll
                        for (int j = 0; j < 26; j++) {
                            FMA2(accA[j], xd[j + q], wA);
                            FMA2(accB[j], xd[j + q], wB);
                        }
                    }
                }
            }
        }
    }
    __syncthreads();

    // ---- conv2 outputs (+bias) to smem: conv_sm[o][row][col], reuse smem
    float* conv_sm = sm;
    if (tx < 26) {
        float b0 = __ldg(&conv2_b[ty * 4 + 0]);
        float b1 = __ldg(&conv2_b[ty * 4 + 1]);
        float b2 = __ldg(&conv2_b[ty * 4 + 2]);
        float b3 = __ldg(&conv2_b[ty * 4 + 3]);
        #pragma unroll
        for (int j = 0; j < 26; j++) {
            conv_sm[((ty * 4 + 0) * 26 + tx) * 26 + j] = lo_f(accA[j]) + b0;
            conv_sm[((ty * 4 + 1) * 26 + tx) * 26 + j] = hi_f(accA[j]) + b1;
            conv_sm[((ty * 4 + 2) * 26 + tx) * 26 + j] = lo_f(accB[j]) + b2;
            conv_sm[((ty * 4 + 3) * 26 + tx) * 26 + j] = hi_f(accB[j]) + b3;
        }
    }
    __syncthreads();

    // ---- pool2 (2x2 max) + spatial mean, warp per ty, deterministic shuffle reduce
    #pragma unroll
    for (int oo = 0; oo < 4; oo++) {
        int o = ty * 4 + oo;
        float s = 0.0f;
        for (int idx = tx; idx < 169; idx += 32) {
            int pi = idx / 13;
            int pj = idx - pi * 13;
            const float* b = conv_sm + (o * 26 + 2 * pi) * 26 + 2 * pj;
            float m = fmaxf(fmaxf(b[0], b[1]), fmaxf(b[26], b[27]));
            s += m;
        }
        #pragma unroll
        for (int off = 16; off; off >>= 1) s += __shfl_down_sync(0xffffffffu, s, off);
        if (tx == 0) mean_sm[o] = s * (1.0f / 169.0f);
    }
    __syncthreads();

    // ---- fc (32 -> 512) + relu
    for (int k = tid; k < 512; k += 256) {
        float v = __ldg(&fc_b[k]);
        const float4* fw = (const float4*)(fc_w + k * 32);
        #pragma unroll
        for (int c4 = 0; c4 < 8; c4++) {
            float4 w4 = __ldg(&fw[c4]);
            v = fmaf(mean_sm[c4 * 4 + 0], w4.x, v);
            v = fmaf(mean_sm[c4 * 4 + 1], w4.y, v);
            v = fmaf(mean_sm[c4 * 4 + 2], w4.z, v);
            v = fmaf(mean_sm[c4 * 4 + 3], w4.w, v);
        }
        out[pair * 512 + k] = fmaxf(v, 0.0f);
    }
}

// ---------------- launch ----------------
extern "C" void kernel_launch(void* const* d_in, const int* in_sizes, int n_in,
                              void* d_out, int out_size) {
    const float* bboxes       = (const float*)d_in[0];
    const int*   object_pairs = (const int*)d_in[3];
    const float* conv1_w      = (const float*)d_in[4];
    const float* conv1_b      = (const float*)d_in[5];
    const float* conv2_w      = (const float*)d_in[6];
    const float* conv2_b      = (const float*)d_in[7];
    const float* fc_w         = (const float*)d_in[8];
    const float* fc_b         = (const float*)d_in[9];
    float* out = (float*)d_out;

    static int attr_set = 0;
    if (!attr_set) {
        cudaFuncSetAttribute(fused_kernel, cudaFuncAttributeMaxDynamicSharedMemorySize, SMEM_BYTES);
        attr_set = 1;
    }

    prep_kernel<<<(64 * 25 * 32 + 128 + 255) / 256, 256>>>(conv2_w, conv1_w);
    fused_kernel<<<NPAIR, dim3(32, 8), SMEM_BYTES>>>(bboxes, object_pairs,
                                                     conv1_b, conv2_b, fc_w, fc_b, out);
}